// round 4
// baseline (speedup 1.0000x reference)
#include <cuda_runtime.h>
#include <math.h>

#define NHEADS 16
#define HSIZE  64
#define NG     8
#define B_     8
#define T_     2048
#define C_     1024
#define GT     256
#define GT1    257

// ---------------- scratch (device globals: no allocation allowed) -------------
__device__ float g_qkv[(size_t)B_ * T_ * 3 * C_];        // 201 MB
__device__ float g_xo [(size_t)B_ * T_ * C_];            // 67 MB
__device__ float g_mean[3][B_][NHEADS][NG][HSIZE];       // q/k/v group means
__device__ float g_attmean[B_][NHEADS][NG][HSIZE];       // attn1 output at mean rows

// ---------------- SGEMM: C[M,N] = A[M,K] * B[K,N], row-major ------------------
#define BM 128
#define BN 128
#define BK 8
#define TM 8
#define TN 8

__global__ __launch_bounds__(256) void sgemm_kernel(
    int M, int N, int K,
    const float* __restrict__ A, const float* __restrict__ B, float* __restrict__ C)
{
    __shared__ float As[BK][BM];   // transposed A tile
    __shared__ float Bs[BK][BN];

    const int tid = threadIdx.x;
    A += (size_t)blockIdx.y * BM * K;
    B += blockIdx.x * BN;
    C += (size_t)blockIdx.y * BM * N + blockIdx.x * BN;

    const int threadCol = tid % (BN / TN);     // 0..15
    const int threadRow = tid / (BN / TN);     // 0..15
    const int innerRowA = tid / (BK / 4);      // 0..127
    const int innerColA = (tid % (BK / 4)) * 4;
    const int innerRowB = tid / (BN / 4);      // 0..7
    const int innerColB = (tid % (BN / 4)) * 4;

    float res[TM * TN] = {0.f};
    float regM[TM], regN[TN];

    for (int bk = 0; bk < K; bk += BK) {
        float4 a4 = *(const float4*)(&A[innerRowA * K + innerColA]);
        As[innerColA + 0][innerRowA] = a4.x;
        As[innerColA + 1][innerRowA] = a4.y;
        As[innerColA + 2][innerRowA] = a4.z;
        As[innerColA + 3][innerRowA] = a4.w;
        *(float4*)(&Bs[innerRowB][innerColB]) =
            *(const float4*)(&B[innerRowB * N + innerColB]);
        __syncthreads();
        A += BK;
        B += (size_t)BK * N;
        #pragma unroll
        for (int k = 0; k < BK; k++) {
            #pragma unroll
            for (int i = 0; i < TM; i++) regM[i] = As[k][threadRow * TM + i];
            #pragma unroll
            for (int j = 0; j < TN; j++) regN[j] = Bs[k][threadCol * TN + j];
            #pragma unroll
            for (int i = 0; i < TM; i++)
                #pragma unroll
                for (int j = 0; j < TN; j++)
                    res[i * TN + j] += regM[i] * regN[j];
        }
        __syncthreads();
    }

    #pragma unroll
    for (int i = 0; i < TM; i++) {
        #pragma unroll
        for (int j = 0; j < TN; j += 4) {
            float4 v = make_float4(res[i * TN + j + 0], res[i * TN + j + 1],
                                   res[i * TN + j + 2], res[i * TN + j + 3]);
            *(float4*)(&C[(threadRow * TM + i) * N + threadCol * TN + j]) = v;
        }
    }
}

// ---------------- group means of q,k,v ---------------------------------------
__global__ __launch_bounds__(192) void means_kernel()
{
    const int g = blockIdx.x, h = blockIdx.y, b = blockIdx.z;
    const int which = threadIdx.x / HSIZE;   // 0=q,1=k,2=v
    const int d     = threadIdx.x % HSIZE;
    const float* base = g_qkv + (size_t)(b * T_ + g * GT) * (3 * C_)
                              + which * C_ + h * HSIZE + d;
    float s = 0.f;
    #pragma unroll 4
    for (int t = 0; t < GT; t++) s += base[(size_t)t * (3 * C_)];
    g_mean[which][b][h][g][d] = s * (1.f / GT);
}

// ---------------- attention 1: per (b,h,g), 257x257 causal --------------------
__global__ __launch_bounds__(288, 1) void attn1_kernel()
{
    extern __shared__ float sm[];
    float* Ks = sm;                 // [257][64]
    float* Vs = sm + GT1 * HSIZE;   // [257][64]

    const int g = blockIdx.x, h = blockIdx.y, b = blockIdx.z;
    const int tid = threadIdx.x;

    for (int idx = tid; idx < GT1 * HSIZE; idx += blockDim.x) {
        const int j = idx >> 6, d = idx & 63;
        float kk, vv;
        if (j < GT) {
            const size_t row = (size_t)(b * T_ + g * GT + j) * (3 * C_) + h * HSIZE + d;
            kk = g_qkv[row + C_];
            vv = g_qkv[row + 2 * C_];
        } else {
            kk = g_mean[1][b][h][g][d];
            vv = g_mean[2][b][h][g][d];
        }
        Ks[idx] = kk;
        Vs[idx] = vv;
    }
    __syncthreads();

    if (tid > GT) return;           // rows 0..256
    const int i = tid;

    float q[HSIZE];
    if (i < GT) {
        const float* qp = g_qkv + (size_t)(b * T_ + g * GT + i) * (3 * C_) + h * HSIZE;
        #pragma unroll
        for (int d4 = 0; d4 < 16; d4++) {
            float4 v = *(const float4*)(qp + 4 * d4);
            q[4 * d4 + 0] = v.x; q[4 * d4 + 1] = v.y;
            q[4 * d4 + 2] = v.z; q[4 * d4 + 3] = v.w;
        }
    } else {
        #pragma unroll
        for (int d = 0; d < HSIZE; d++) q[d] = g_mean[0][b][h][g][d];
    }

    const int jmax = (i < GT) ? i : GT;   // causal: mean row attends everything
    float m = -1e30f, l = 0.f;
    float acc[HSIZE];
    #pragma unroll
    for (int d = 0; d < HSIZE; d++) acc[d] = 0.f;

    for (int j = 0; j <= jmax; j++) {
        const float4* kp = (const float4*)(Ks + j * HSIZE);
        float s = 0.f;
        #pragma unroll
        for (int d4 = 0; d4 < 16; d4++) {
            float4 kv = kp[d4];
            s += q[4 * d4 + 0] * kv.x + q[4 * d4 + 1] * kv.y
               + q[4 * d4 + 2] * kv.z + q[4 * d4 + 3] * kv.w;
        }
        s *= 0.125f;   // 1/sqrt(64)
        const float mn   = fmaxf(m, s);
        const float corr = __expf(m - mn);
        const float p    = __expf(s - mn);
        l = l * corr + p;
        const float4* vp = (const float4*)(Vs + j * HSIZE);
        #pragma unroll
        for (int d4 = 0; d4 < 16; d4++) {
            float4 vv = vp[d4];
            acc[4 * d4 + 0] = acc[4 * d4 + 0] * corr + p * vv.x;
            acc[4 * d4 + 1] = acc[4 * d4 + 1] * corr + p * vv.y;
            acc[4 * d4 + 2] = acc[4 * d4 + 2] * corr + p * vv.z;
            acc[4 * d4 + 3] = acc[4 * d4 + 3] * corr + p * vv.w;
        }
        m = mn;
    }
    const float inv = 1.f / l;

    if (i < GT) {
        float* op = g_xo + (size_t)(b * T_ + g * GT + i) * C_ + h * HSIZE;
        #pragma unroll
        for (int d4 = 0; d4 < 16; d4++) {
            float4 v = make_float4(acc[4 * d4 + 0] * inv, acc[4 * d4 + 1] * inv,
                                   acc[4 * d4 + 2] * inv, acc[4 * d4 + 3] * inv);
            *(float4*)(op + 4 * d4) = v;
        }
    } else {
        #pragma unroll
        for (int d = 0; d < HSIZE; d++) g_attmean[b][h][g][d] = acc[d] * inv;
    }
}

// ---------------- attention 2 (7x7 over group means) + y outputs --------------
__global__ __launch_bounds__(64) void attn2_kernel(float* __restrict__ out)
{
    __shared__ float qs[7 * 64], ks[7 * 64], vs[7 * 64];
    const int h = blockIdx.x, b = blockIdx.y;
    const int tid = threadIdx.x;   // 64 threads = one d each

    for (int g = 0; g < 7; g++) {
        qs[g * 64 + tid] = g_mean[0][b][h][g][tid];
        ks[g * 64 + tid] = g_mean[1][b][h][g][tid];
        vs[g * 64 + tid] = g_attmean[b][h][g][tid];
    }
    __syncthreads();

    const size_t YQ   = (size_t)B_ * T_ * C_;                 // 16777216
    const size_t YLEN = (size_t)B_ * NHEADS * 7 * HSIZE;      // 57344
    for (int g = 0; g < 7; g++) {
        const size_t o = ((size_t)(b * NHEADS + h) * 7 + g) * HSIZE + tid;
        out[YQ + o]        = qs[g * 64 + tid];   // yq
        out[YQ + YLEN + o] = ks[g * 64 + tid];   // yk
    }

    if (tid < 7) {
        const int i = tid;
        float sc[7];
        float m = -1e30f;
        for (int j = 0; j <= i; j++) {
            float s = 0.f;
            #pragma unroll
            for (int d = 0; d < 64; d++) s += qs[i * 64 + d] * ks[j * 64 + d];
            s *= 0.125f;
            sc[j] = s;
            m = fmaxf(m, s);
        }
        float l = 0.f;
        for (int j = 0; j <= i; j++) { sc[j] = __expf(sc[j] - m); l += sc[j]; }
        const float inv = 1.f / l;
        for (int d = 0; d < 64; d++) {
            float a = 0.f;
            for (int j = 0; j <= i; j++) a += sc[j] * vs[j * 64 + d];
            out[YQ + 2 * YLEN + ((size_t)(b * NHEADS + h) * 7 + i) * HSIZE + d] = a * inv;
        }
    }
}

// ---------------- launch ------------------------------------------------------
extern "C" void kernel_launch(void* const* d_in, const int* in_sizes, int n_in,
                              void* d_out, int out_size)
{
    const float* x      = (const float*)d_in[0];
    const float* W_attn = (const float*)d_in[1];
    const float* W_proj = (const float*)d_in[2];
    float* out = (float*)d_out;

    static float* p_qkv = nullptr;
    static float* p_xo  = nullptr;
    if (!p_qkv) {   // first call is the (uncaptured) correctness run
        cudaGetSymbolAddress((void**)&p_qkv, g_qkv);
        cudaGetSymbolAddress((void**)&p_xo,  g_xo);
        cudaFuncSetAttribute(attn1_kernel,
            cudaFuncAttributeMaxDynamicSharedMemorySize,
            2 * GT1 * HSIZE * (int)sizeof(float));
    }

    // 1) qkv = x @ W_attn   [16384,1024] x [1024,3072]
    {
        dim3 grid((3 * C_) / BN, (B_ * T_) / BM);
        sgemm_kernel<<<grid, 256>>>(B_ * T_, 3 * C_, C_, x, W_attn, p_qkv);
    }
    // 2) group means of q,k,v
    means_kernel<<<dim3(NG, NHEADS, B_), 192>>>();
    // 3) grouped causal attention (writes g_xo + g_attmean)
    attn1_kernel<<<dim3(NG, NHEADS, B_), 288,
                   2 * GT1 * HSIZE * sizeof(float)>>>();
    // 4) group-summary attention + yq/yk/yv
    attn2_kernel<<<dim3(NHEADS, B_), 64>>>(out);
    // 5) out = xo @ W_proj  [16384,1024] x [1024,1024]
    {
        dim3 grid(C_ / BN, (B_ * T_) / BM);
        sgemm_kernel<<<grid, 256>>>(B_ * T_, C_, C_, p_xo, W_proj, out);
    }
}

// round 7
// speedup vs baseline: 2.3951x; 2.3951x over previous
#include <cuda_runtime.h>
#include <math.h>

#define NHEADS 16
#define HSIZE  64
#define NG     8
#define B_     8
#define T_     2048
#define C_     1024
#define GT     256
#define GT1    257

// ---------------- scratch (device globals: no allocation allowed) -------------
__device__ float g_qkv[(size_t)B_ * T_ * 3 * C_];        // 201 MB
__device__ float g_xo [(size_t)B_ * T_ * C_];            // 67 MB
__device__ float g_mean[3][B_][NHEADS][NG][HSIZE];       // q/k/v group means
__device__ float g_attmean[B_][NHEADS][NG][HSIZE];       // attn1 output at mean rows

// ---------------- TF32 tensor-core GEMM ---------------------------------------
// C[M,N] = A[M,K] * B[K,N], row-major. Block tile 128x128, K-chunk 32.
// 8 warps: warp tile 64x32, built from 4x4 mma.m16n8k8.tf32.

__device__ __forceinline__ float to_tf32(float x) {
    float y;
    asm("cvt.rna.tf32.f32 %0, %1;" : "=f"(y) : "f"(x));
    return y;
}

__device__ __forceinline__ void mma_tf32(float* c, const float* a, const float* b) {
    asm volatile(
        "mma.sync.aligned.m16n8k8.row.col.f32.tf32.tf32.f32 "
        "{%0,%1,%2,%3}, {%4,%5,%6,%7}, {%8,%9}, {%0,%1,%2,%3};\n"
        : "+f"(c[0]), "+f"(c[1]), "+f"(c[2]), "+f"(c[3])
        : "r"(__float_as_uint(a[0])), "r"(__float_as_uint(a[1])),
          "r"(__float_as_uint(a[2])), "r"(__float_as_uint(a[3])),
          "r"(__float_as_uint(b[0])), "r"(__float_as_uint(b[1])));
}

__global__ __launch_bounds__(256) void tf32gemm_kernel(
    int M, int N, int K,
    const float* __restrict__ A, const float* __restrict__ B, float* __restrict__ C)
{
    __shared__ float As[128][36];   // [m][k], pad 4 -> conflict-free frag loads
    __shared__ float Bs[32][136];   // [k][n], pad 8 -> conflict-free frag loads

    const int tid  = threadIdx.x;
    const int lane = tid & 31;
    const int warp = tid >> 5;
    const int warpRow = (warp & 1) * 64;   // m offset of warp tile
    const int warpCol = (warp >> 1) * 32;  // n offset of warp tile
    const int g = lane >> 2;               // groupID
    const int t = lane & 3;                // threadID_in_group

    A += (size_t)blockIdx.y * 128 * K;
    B += blockIdx.x * 128;
    C += (size_t)blockIdx.y * 128 * N + blockIdx.x * 128;

    float acc[4][4][4];
    #pragma unroll
    for (int i = 0; i < 4; i++)
        #pragma unroll
        for (int j = 0; j < 4; j++)
            #pragma unroll
            for (int r = 0; r < 4; r++) acc[i][j][r] = 0.f;

    const int aRow = tid >> 3;          // 0..31 (4 passes of 32 rows)
    const int aCol = (tid & 7) * 4;     // 0..28
    const int bRow = tid >> 5;          // 0..7  (4 passes of 8 rows)
    const int bCol = (tid & 31) * 4;    // 0..124

    for (int k0 = 0; k0 < K; k0 += 32) {
        #pragma unroll
        for (int i = 0; i < 4; i++) {
            float4 v = *(const float4*)(&A[(size_t)(aRow + 32 * i) * K + k0 + aCol]);
            As[aRow + 32 * i][aCol + 0] = to_tf32(v.x);
            As[aRow + 32 * i][aCol + 1] = to_tf32(v.y);
            As[aRow + 32 * i][aCol + 2] = to_tf32(v.z);
            As[aRow + 32 * i][aCol + 3] = to_tf32(v.w);
        }
        #pragma unroll
        for (int i = 0; i < 4; i++) {
            float4 v = *(const float4*)(&B[(size_t)(k0 + bRow + 8 * i) * N + bCol]);
            Bs[bRow + 8 * i][bCol + 0] = to_tf32(v.x);
            Bs[bRow + 8 * i][bCol + 1] = to_tf32(v.y);
            Bs[bRow + 8 * i][bCol + 2] = to_tf32(v.z);
            Bs[bRow + 8 * i][bCol + 3] = to_tf32(v.w);
        }
        __syncthreads();

        #pragma unroll
        for (int kk = 0; kk < 32; kk += 8) {
            float afr[4][4];
            #pragma unroll
            for (int mt = 0; mt < 4; mt++) {
                const int r = warpRow + mt * 16;
                afr[mt][0] = As[r + g    ][kk + t    ];
                afr[mt][1] = As[r + g + 8][kk + t    ];
                afr[mt][2] = As[r + g    ][kk + t + 4];
                afr[mt][3] = As[r + g + 8][kk + t + 4];
            }
            float bfr[4][2];
            #pragma unroll
            for (int nt = 0; nt < 4; nt++) {
                const int c = warpCol + nt * 8 + g;
                bfr[nt][0] = Bs[kk + t    ][c];
                bfr[nt][1] = Bs[kk + t + 4][c];
            }
            #pragma unroll
            for (int mt = 0; mt < 4; mt++)
                #pragma unroll
                for (int nt = 0; nt < 4; nt++)
                    mma_tf32(acc[mt][nt], afr[mt], bfr[nt]);
        }
        __syncthreads();
    }

    #pragma unroll
    for (int mt = 0; mt < 4; mt++) {
        const int r0 = warpRow + mt * 16 + g;
        #pragma unroll
        for (int nt = 0; nt < 4; nt++) {
            const int c0 = warpCol + nt * 8 + 2 * t;
            *(float2*)(&C[(size_t)r0 * N + c0]) =
                make_float2(acc[mt][nt][0], acc[mt][nt][1]);
            *(float2*)(&C[(size_t)(r0 + 8) * N + c0]) =
                make_float2(acc[mt][nt][2], acc[mt][nt][3]);
        }
    }
}

// ---------------- group means of q,k,v ---------------------------------------
__global__ __launch_bounds__(192) void means_kernel()
{
    const int g = blockIdx.x, h = blockIdx.y, b = blockIdx.z;
    const int which = threadIdx.x / HSIZE;   // 0=q,1=k,2=v
    const int d     = threadIdx.x % HSIZE;
    const float* base = g_qkv + (size_t)(b * T_ + g * GT) * (3 * C_)
                              + which * C_ + h * HSIZE + d;
    float s = 0.f;
    #pragma unroll 4
    for (int t = 0; t < GT; t++) s += base[(size_t)t * (3 * C_)];
    g_mean[which][b][h][g][d] = s * (1.f / GT);
}

// ---------------- attention 1: per (b,h,g), 257x257 causal --------------------
__global__ __launch_bounds__(288, 1) void attn1_kernel()
{
    extern __shared__ float sm[];
    float* Ks = sm;                 // [257][64]
    float* Vs = sm + GT1 * HSIZE;   // [257][64]

    const int g = blockIdx.x, h = blockIdx.y, b = blockIdx.z;
    const int tid = threadIdx.x;

    for (int idx = tid; idx < GT1 * HSIZE; idx += blockDim.x) {
        const int j = idx >> 6, d = idx & 63;
        float kk, vv;
        if (j < GT) {
            const size_t row = (size_t)(b * T_ + g * GT + j) * (3 * C_) + h * HSIZE + d;
            kk = g_qkv[row + C_];
            vv = g_qkv[row + 2 * C_];
        } else {
            kk = g_mean[1][b][h][g][d];
            vv = g_mean[2][b][h][g][d];
        }
        Ks[idx] = kk;
        Vs[idx] = vv;
    }
    __syncthreads();

    if (tid > GT) return;           // rows 0..256
    const int i = tid;

    float q[HSIZE];
    if (i < GT) {
        const float* qp = g_qkv + (size_t)(b * T_ + g * GT + i) * (3 * C_) + h * HSIZE;
        #pragma unroll
        for (int d4 = 0; d4 < 16; d4++) {
            float4 v = *(const float4*)(qp + 4 * d4);
            q[4 * d4 + 0] = v.x; q[4 * d4 + 1] = v.y;
            q[4 * d4 + 2] = v.z; q[4 * d4 + 3] = v.w;
        }
    } else {
        #pragma unroll
        for (int d = 0; d < HSIZE; d++) q[d] = g_mean[0][b][h][g][d];
    }

    const int jmax = (i < GT) ? i : GT;   // causal: mean row attends everything
    float m = -1e30f, l = 0.f;
    float acc[HSIZE];
    #pragma unroll
    for (int d = 0; d < HSIZE; d++) acc[d] = 0.f;

    for (int j = 0; j <= jmax; j++) {
        const float4* kp = (const float4*)(Ks + j * HSIZE);
        float s = 0.f;
        #pragma unroll
        for (int d4 = 0; d4 < 16; d4++) {
            float4 kv = kp[d4];
            s += q[4 * d4 + 0] * kv.x + q[4 * d4 + 1] * kv.y
               + q[4 * d4 + 2] * kv.z + q[4 * d4 + 3] * kv.w;
        }
        s *= 0.125f;   // 1/sqrt(64)
        const float mn   = fmaxf(m, s);
        const float corr = __expf(m - mn);
        const float p    = __expf(s - mn);
        l = l * corr + p;
        const float4* vp = (const float4*)(Vs + j * HSIZE);
        #pragma unroll
        for (int d4 = 0; d4 < 16; d4++) {
            float4 vv = vp[d4];
            acc[4 * d4 + 0] = acc[4 * d4 + 0] * corr + p * vv.x;
            acc[4 * d4 + 1] = acc[4 * d4 + 1] * corr + p * vv.y;
            acc[4 * d4 + 2] = acc[4 * d4 + 2] * corr + p * vv.z;
            acc[4 * d4 + 3] = acc[4 * d4 + 3] * corr + p * vv.w;
        }
        m = mn;
    }
    const float inv = 1.f / l;

    if (i < GT) {
        float* op = g_xo + (size_t)(b * T_ + g * GT + i) * C_ + h * HSIZE;
        #pragma unroll
        for (int d4 = 0; d4 < 16; d4++) {
            float4 v = make_float4(acc[4 * d4 + 0] * inv, acc[4 * d4 + 1] * inv,
                                   acc[4 * d4 + 2] * inv, acc[4 * d4 + 3] * inv);
            *(float4*)(op + 4 * d4) = v;
        }
    } else {
        #pragma unroll
        for (int d = 0; d < HSIZE; d++) g_attmean[b][h][g][d] = acc[d] * inv;
    }
}

// ---------------- attention 2 (7x7 over group means) + y outputs --------------
__global__ __launch_bounds__(64) void attn2_kernel(float* __restrict__ out)
{
    __shared__ float qs[7 * 64], ks[7 * 64], vs[7 * 64];
    const int h = blockIdx.x, b = blockIdx.y;
    const int tid = threadIdx.x;   // 64 threads = one d each

    for (int g = 0; g < 7; g++) {
        qs[g * 64 + tid] = g_mean[0][b][h][g][tid];
        ks[g * 64 + tid] = g_mean[1][b][h][g][tid];
        vs[g * 64 + tid] = g_attmean[b][h][g][tid];
    }
    __syncthreads();

    const size_t YQ   = (size_t)B_ * T_ * C_;                 // 16777216
    const size_t YLEN = (size_t)B_ * NHEADS * 7 * HSIZE;      // 57344
    for (int g = 0; g < 7; g++) {
        const size_t o = ((size_t)(b * NHEADS + h) * 7 + g) * HSIZE + tid;
        out[YQ + o]        = qs[g * 64 + tid];   // yq
        out[YQ + YLEN + o] = ks[g * 64 + tid];   // yk
    }

    if (tid < 7) {
        const int i = tid;
        float sc[7];
        float m = -1e30f;
        for (int j = 0; j <= i; j++) {
            float s = 0.f;
            #pragma unroll
            for (int d = 0; d < 64; d++) s += qs[i * 64 + d] * ks[j * 64 + d];
            s *= 0.125f;
            sc[j] = s;
            m = fmaxf(m, s);
        }
        float l = 0.f;
        for (int j = 0; j <= i; j++) { sc[j] = __expf(sc[j] - m); l += sc[j]; }
        const float inv = 1.f / l;
        for (int d = 0; d < 64; d++) {
            float a = 0.f;
            for (int j = 0; j <= i; j++) a += sc[j] * vs[j * 64 + d];
            out[YQ + 2 * YLEN + ((size_t)(b * NHEADS + h) * 7 + i) * HSIZE + d] = a * inv;
        }
    }
}

// ---------------- launch ------------------------------------------------------
extern "C" void kernel_launch(void* const* d_in, const int* in_sizes, int n_in,
                              void* d_out, int out_size)
{
    const float* x      = (const float*)d_in[0];
    const float* W_attn = (const float*)d_in[1];
    const float* W_proj = (const float*)d_in[2];
    float* out = (float*)d_out;

    static float* p_qkv = nullptr;
    static float* p_xo  = nullptr;
    if (!p_qkv) {   // first call is the (uncaptured) correctness run
        cudaGetSymbolAddress((void**)&p_qkv, g_qkv);
        cudaGetSymbolAddress((void**)&p_xo,  g_xo);
        cudaFuncSetAttribute(attn1_kernel,
            cudaFuncAttributeMaxDynamicSharedMemorySize,
            2 * GT1 * HSIZE * (int)sizeof(float));
    }

    // 1) qkv = x @ W_attn   [16384,1024] x [1024,3072]  (TF32 tensor cores)
    {
        dim3 grid((3 * C_) / 128, (B_ * T_) / 128);
        tf32gemm_kernel<<<grid, 256>>>(B_ * T_, 3 * C_, C_, x, W_attn, p_qkv);
    }
    // 2) group means of q,k,v
    means_kernel<<<dim3(NG, NHEADS, B_), 192>>>();
    // 3) grouped causal attention (writes g_xo + g_attmean)
    attn1_kernel<<<dim3(NG, NHEADS, B_), 288,
                   2 * GT1 * HSIZE * sizeof(float)>>>();
    // 4) group-summary attention + yq/yk/yv
    attn2_kernel<<<dim3(NHEADS, B_), 64>>>(out);
    // 5) out = xo @ W_proj  [16384,1024] x [1024,1024]  (TF32 tensor cores)
    {
        dim3 grid(C_ / 128, (B_ * T_) / 128);
        tf32gemm_kernel<<<grid, 256>>>(B_ * T_, C_, C_, p_xo, W_proj, out);
    }
}